// round 1
// baseline (speedup 1.0000x reference)
#include <cuda_runtime.h>
#include <math.h>

#define BATCH 128
#define CH 128
#define NN 170
#define TT 12
#define SCALE 0.08838834764831845f  /* 1/sqrt(128) */
#define PAD 172                     /* pitch for Ed smem: 4-aligned, stride*4 conflict-free */
#define KROWS 192                   /* 170 rounded up to 32*6 so k=lane+32j loads stay in-bounds */

__device__ float g_xs[BATCH * NN * CH];      /* [b][n][c] */
__device__ float g_Ed[BATCH * NN * NN];      /* [b][n][m] */
__device__ float g_probs[BATCH * NN * NN];   /* [b][n][k] */

/* ------------------------------------------------------------------ */
/* Kernel 1: xs[b][n][c] = sum_t x[b][c][n][t]  (reduce T, transpose) */
/* grid: (4 c-tiles, BATCH), 256 threads                               */
/* ------------------------------------------------------------------ */
__global__ void k_reduce(const float* __restrict__ x) {
    __shared__ float s[32][NN + 1];   /* [c_local][n], pitch 171 (odd) -> conflict-free */
    const int b  = blockIdx.y;
    const int c0 = blockIdx.x * 32;
    const int tid = threadIdx.x;

    /* phase 1: load 12 contiguous floats per (c,n), reduce */
    for (int i = tid; i < 32 * NN; i += 256) {
        const int c_l = i / NN;
        const int n   = i - c_l * NN;
        const float4* base = (const float4*)(x + ((size_t)((b * CH + c0 + c_l) * NN + n)) * TT);
        float4 v0 = base[0], v1 = base[1], v2 = base[2];
        float sum = v0.x + v0.y + v0.z + v0.w
                  + v1.x + v1.y + v1.z + v1.w
                  + v2.x + v2.y + v2.z + v2.w;
        s[c_l][n] = sum;
    }
    __syncthreads();

    /* phase 2: transposed coalesced store */
    for (int i = tid; i < NN * 32; i += 256) {
        const int n   = i >> 5;       /* i / 32 */
        const int c_l = i & 31;
        g_xs[((size_t)(b * NN + n)) * CH + c0 + c_l] = s[c_l][n];
    }
}

/* ------------------------------------------------------------------ */
/* Kernel 2: Ed[b] = tanh(xs[b] @ E_s)   [170,128]x[128,170]           */
/* grid: (3,3,BATCH), 256 threads, 64x64 tile, 4x4 microtile           */
/* ------------------------------------------------------------------ */
__global__ void k_gemm1(const float* __restrict__ Es) {
    __shared__ float As[16][65];  /* As[kk][row] */
    __shared__ float Bs[16][65];  /* Bs[kk][col] */

    const int b   = blockIdx.z;
    const int row0 = blockIdx.y * 64;
    const int col0 = blockIdx.x * 64;
    const int tid = threadIdx.x;
    const int tx = tid & 15;
    const int ty = tid >> 4;

    const float* A = g_xs + (size_t)b * NN * CH;
    float*       Cm = g_Ed + (size_t)b * NN * NN;

    float acc[4][4] = {};

    for (int kt = 0; kt < CH; kt += 16) {
        for (int l = tid; l < 64 * 16; l += 256) {
            const int r  = l >> 4;
            const int kk = l & 15;
            const int gr = row0 + r;
            As[kk][r] = (gr < NN) ? A[gr * CH + kt + kk] : 0.f;
        }
        for (int l = tid; l < 16 * 64; l += 256) {
            const int kk = l >> 6;
            const int cc = l & 63;
            const int gc = col0 + cc;
            Bs[kk][cc] = (gc < NN) ? Es[(kt + kk) * NN + gc] : 0.f;
        }
        __syncthreads();
#pragma unroll
        for (int kk = 0; kk < 16; kk++) {
            float a[4], bb[4];
#pragma unroll
            for (int i = 0; i < 4; i++) a[i] = As[kk][ty * 4 + i];
#pragma unroll
            for (int j = 0; j < 4; j++) bb[j] = Bs[kk][tx * 4 + j];
#pragma unroll
            for (int i = 0; i < 4; i++)
#pragma unroll
                for (int j = 0; j < 4; j++)
                    acc[i][j] = fmaf(a[i], bb[j], acc[i][j]);
        }
        __syncthreads();
    }

#pragma unroll
    for (int i = 0; i < 4; i++) {
        const int gr = row0 + ty * 4 + i;
        if (gr >= NN) continue;
#pragma unroll
        for (int j = 0; j < 4; j++) {
            const int gc = col0 + tx * 4 + j;
            if (gc < NN) Cm[gr * NN + gc] = tanhf(acc[i][j]);
        }
    }
}

/* ------------------------------------------------------------------ */
/* Kernel 3: per batch: scores = relu(Ed Ed^T / sqrt(C)); softmax rows */
/* grid: BATCH blocks, 256 threads, 132KB dyn smem                     */
/* ------------------------------------------------------------------ */
__global__ void k_scores() {
    extern __shared__ float Ed_s[];   /* [KROWS][PAD] */
    const int b    = blockIdx.x;
    const int tid  = threadIdx.x;
    const int warp = tid >> 5;
    const int lane = tid & 31;

    /* zero (covers pad rows/cols so OOB k-rows contribute 0) */
    float4 z4 = make_float4(0.f, 0.f, 0.f, 0.f);
    for (int i = tid; i < KROWS * PAD / 4; i += 256)
        ((float4*)Ed_s)[i] = z4;
    __syncthreads();

    const float* Edb = g_Ed + (size_t)b * NN * NN;
    for (int i = tid; i < NN * NN; i += 256) {
        const int r = i / NN;
        const int m = i - r * NN;
        Ed_s[r * PAD + m] = Edb[i];
    }
    __syncthreads();

    for (int n0 = warp * 8; n0 < NN; n0 += 64) {
        float acc[8][6] = {};

        /* main dot-product loop, m in groups of 4 (168 of 170) */
        for (int m = 0; m + 4 <= NN; m += 4) {
            float4 a[8];
#pragma unroll
            for (int r = 0; r < 8; r++)
                a[r] = *(const float4*)&Ed_s[(n0 + r) * PAD + m];
#pragma unroll
            for (int j = 0; j < 6; j++) {
                const int k = lane + 32 * j;
                float4 bb = *(const float4*)&Ed_s[k * PAD + m];
#pragma unroll
                for (int r = 0; r < 8; r++) {
                    acc[r][j] = fmaf(a[r].x, bb.x, acc[r][j]);
                    acc[r][j] = fmaf(a[r].y, bb.y, acc[r][j]);
                    acc[r][j] = fmaf(a[r].z, bb.z, acc[r][j]);
                    acc[r][j] = fmaf(a[r].w, bb.w, acc[r][j]);
                }
            }
        }
        /* remainder m = 168, 169 */
        for (int m = (NN / 4) * 4; m < NN; m++) {
            float a_s[8];
#pragma unroll
            for (int r = 0; r < 8; r++) a_s[r] = Ed_s[(n0 + r) * PAD + m];
#pragma unroll
            for (int j = 0; j < 6; j++) {
                const int k = lane + 32 * j;
                const float bb = Ed_s[k * PAD + m];
#pragma unroll
                for (int r = 0; r < 8; r++)
                    acc[r][j] = fmaf(a_s[r], bb, acc[r][j]);
            }
        }

        /* per-row relu + softmax + store */
#pragma unroll
        for (int r = 0; r < 8; r++) {
            const int n = n0 + r;
            if (n >= NN) break;   /* uniform across warp */

            float v[6];
            float vmax = -1.f;
#pragma unroll
            for (int j = 0; j < 6; j++) {
                const int k = lane + 32 * j;
                if (k < NN) {
                    const float sv = acc[r][j] * SCALE;
                    v[j] = sv > 0.f ? sv : 0.f;
                    vmax = fmaxf(vmax, v[j]);
                } else {
                    v[j] = -1.f;
                }
            }
#pragma unroll
            for (int off = 16; off > 0; off >>= 1)
                vmax = fmaxf(vmax, __shfl_xor_sync(0xffffffffu, vmax, off));

            float e[6];
            float ssum = 0.f;
#pragma unroll
            for (int j = 0; j < 6; j++) {
                const int k = lane + 32 * j;
                if (k < NN) {
                    e[j] = expf(v[j] - vmax);
                    ssum += e[j];
                }
            }
#pragma unroll
            for (int off = 16; off > 0; off >>= 1)
                ssum += __shfl_xor_sync(0xffffffffu, ssum, off);

            const float inv = 1.f / ssum;
            float* outp = g_probs + ((size_t)b * NN + n) * NN;
#pragma unroll
            for (int j = 0; j < 6; j++) {
                const int k = lane + 32 * j;
                if (k < NN) outp[k] = e[j] * inv;
            }
        }
    }
}

/* ------------------------------------------------------------------ */
/* Kernel 4: mean over batch + threshold                               */
/* ------------------------------------------------------------------ */
__global__ void k_final(float* __restrict__ out) {
    const int i = blockIdx.x * blockDim.x + threadIdx.x;
    if (i >= NN * NN) return;
    float s = 0.f;
    for (int b = 0; b < BATCH; b++)
        s += g_probs[(size_t)b * NN * NN + i];
    out[i] = (s * (1.0f / BATCH) > 0.5f) ? 1.0f : 0.0f;
}

/* ------------------------------------------------------------------ */
extern "C" void kernel_launch(void* const* d_in, const int* in_sizes, int n_in,
                              void* d_out, int out_size) {
    const float* x  = (const float*)d_in[0];
    const float* Es = (const float*)d_in[1];
    float* out = (float*)d_out;

    cudaFuncSetAttribute(k_scores, cudaFuncAttributeMaxDynamicSharedMemorySize,
                         KROWS * PAD * sizeof(float));

    k_reduce<<<dim3(4, BATCH), 256>>>(x);
    k_gemm1<<<dim3(3, 3, BATCH), 256>>>(Es);
    k_scores<<<BATCH, 256, KROWS * PAD * sizeof(float)>>>();
    k_final<<<(NN * NN + 255) / 256, 256>>>(out);
}